// round 13
// baseline (speedup 1.0000x reference)
#include <cuda_runtime.h>
#include <cuda_fp16.h>
#include <cstdint>

// NF4 linear, 3-kernel plan (mma.sync path; tcgen05 unavailable on compute_103):
//   1) convert X fp32 -> fp16, TILE-MAJOR + PRE-SWIZZLED scratch
//   2) dequantize W -> fp16, TILE-MAJOR + PRE-SWIZZLED scratch
//   3) PERSISTENT GEMM: grid = 444 (3 CTAs/SM), each CTA loops tiles with a
//      continuous 2-stage bulk-copy pipeline across tile boundaries.
// out = fp16(XT @ WT^T) + fp16(bias), emitted fp32.

typedef unsigned int u32;

#define BM 128
#define BN 128
#define BK 64
#define THREADS 128
#define KDIM 4096
#define NOUT 11008
#define TILE_BYTES 16384                       // 128 rows x 128B (64 halfs)
#define NTILES 2752                            // 32 m-tiles * 86 n-tiles
#define GRID 444                               // 148 SMs * 3 CTAs

// tile-major pre-swizzled scratch
__device__ __align__(1024) unsigned char XT[32u * 64u * 16384u];   // 32 MB
__device__ __align__(1024) unsigned char WT[86u * 64u * 16384u];   // 90 MB

__constant__ float c_nf4[16] = {
    -1.0f, -0.6961928009986877f, -0.5250730514526367f, -0.39491748809814453f,
    -0.28444138169288635f, -0.18477343022823334f, -0.09105003625154495f, 0.0f,
    0.07958029955625534f, 0.16093020141124725f, 0.24611230194568634f,
    0.33791524171829224f, 0.44070982933044434f, 0.5626170039176941f,
    0.8072066307067871f, 1.0f};

__device__ __forceinline__ u32 sw128(u32 off) { return off ^ ((off >> 3) & 0x70); }

#define MBAR_INIT(a, c) \
    asm volatile("mbarrier.init.shared.b64 [%0], %1;" :: "r"(a), "r"(c) : "memory")
#define MBAR_EXPECT_TX(a, tx) \
    asm volatile("mbarrier.arrive.expect_tx.shared.b64 _, [%0], %1;" \
                 :: "r"(a), "r"(tx) : "memory")
#define MBAR_WAIT(a, par) do {                                                       \
    u32 _mb = (a); u32 _p = (par); u32 _done;                                        \
    asm volatile("{ .reg .pred p; mbarrier.try_wait.parity.shared.b64 p, [%1], %2;"  \
                 " selp.b32 %0,1,0,p; }" : "=r"(_done) : "r"(_mb), "r"(_p) : "memory"); \
    while (!_done) {                                                                 \
        asm volatile("{ .reg .pred p; mbarrier.try_wait.parity.shared.b64 p, [%1], %2;" \
                     " selp.b32 %0,1,0,p; }" : "=r"(_done) : "r"(_mb), "r"(_p) : "memory"); \
    }                                                                                \
} while (0)

__device__ __forceinline__ void bulk_cp(u32 dst, const void* src, u32 bytes, u32 bar) {
    asm volatile(
        "cp.async.bulk.shared::cta.global.mbarrier::complete_tx::bytes "
        "[%0], [%1], %2, [%3];\n"
        :: "r"(dst), "l"(src), "r"(bytes), "r"(bar) : "memory");
}

// ---------------- prep kernels (tile-major, pre-swizzled output) ----------------
__global__ __launch_bounds__(256) void convert_x_kernel(const float* __restrict__ X) {
    int t = blockIdx.x * 256 + threadIdx.x;        // 2M chunks
    int tile = t >> 10, c = t & 1023;
    int bm = tile >> 6, kt = tile & 63;
    int r = c >> 3, j = c & 7;
    const float* xp = X + (size_t)(bm * 128 + r) * KDIM + kt * 64 + j * 8;
    float4 a = *(const float4*)xp, b = *(const float4*)(xp + 4);
    __half2 h0 = __floats2half2_rn(a.x, a.y), h1 = __floats2half2_rn(a.z, a.w);
    __half2 h2 = __floats2half2_rn(b.x, b.y), h3 = __floats2half2_rn(b.z, b.w);
    uint4 o;
    o.x = *(u32*)&h0; o.y = *(u32*)&h1; o.z = *(u32*)&h2; o.w = *(u32*)&h3;
    *(uint4*)(XT + (size_t)tile * TILE_BYTES + sw128(r * 128 + j * 16)) = o;
}

__global__ __launch_bounds__(256) void dequant_w_kernel(const int* __restrict__ WP,
                                                        const float* __restrict__ AM) {
    __shared__ float tab[16];
    if (threadIdx.x < 16) tab[threadIdx.x] = c_nf4[threadIdx.x];
    __syncthreads();
    int t = blockIdx.x * 256 + threadIdx.x;        // 5.63M chunks
    int tile = t >> 10, c = t & 1023;
    int bn = tile >> 6, kt = tile & 63;
    int r = c >> 3, j = c & 7;
    int n = bn * 128 + r;
    float s = AM[(size_t)n * 64 + kt];             // kt == absmax block index
    int4 v = *(const int4*)(WP + (size_t)n * 2048 + kt * 32 + j * 4);
    int vv[4] = {v.x, v.y, v.z, v.w};
    u32 o[4];
    #pragma unroll
    for (int q = 0; q < 4; q++) {                  // hi nibble = even elem
        __half2 h = __floats2half2_rn(tab[(vv[q] >> 4) & 15] * s,
                                      tab[vv[q] & 15] * s);
        o[q] = *(u32*)&h;
    }
    uint4 w; w.x = o[0]; w.y = o[1]; w.z = o[2]; w.w = o[3];
    *(uint4*)(WT + (size_t)tile * TILE_BYTES + sw128(r * 128 + j * 16)) = w;
}

// ---------------- persistent GEMM ----------------
#define STAGEB (2 * TILE_BYTES)                    // A+B per stage = 32768
#define SMEM_BYTES (1024 + 2 * STAGEB)             // 66560

// tile id tv -> (bm, bn) with the L2-friendly swizzle (16 m-tiles sweep all N)
__device__ __forceinline__ void tile_map(int tv, int& bm, int& bn) {
    int g = tv / 1376, r = tv % 1376;              // 16 * 86
    bm = g * 16 + (r & 15);
    bn = r >> 4;
}

__global__ __launch_bounds__(THREADS, 3)
void nf4_mma_gemm(const float* __restrict__ BIAS, float* __restrict__ OUT)
{
    extern __shared__ unsigned char smem[];
    u32 sbase;
    asm("{ .reg .u64 t; cvta.to.shared.u64 t, %1; cvt.u32.u64 %0, t; }"
        : "=r"(sbase) : "l"(smem));
    const u32 BAR0 = sbase, BAR1 = sbase + 8;
    const u32 TILES = sbase + 1024;

    const int tid = threadIdx.x;
    const int lane = tid & 31;
    const int wid = tid >> 5;
    const int wm = wid >> 1;
    const int wn = wid & 1;
    const int bid = blockIdx.x;

    const int ntiles = (NTILES - bid + GRID - 1) / GRID;   // 7 or 6
    const int total = ntiles * 64;                         // global steps

    if (tid == 0) { MBAR_INIT(BAR0, 1); MBAR_INIT(BAR1, 1); }
    __syncthreads();

    // prefetch for global step ls (tile = ls>>6, kt = ls&63)
    auto prefetch = [&](int ls) {
        int tv = bid + (ls >> 6) * GRID;
        int kt = ls & 63;
        int pbm, pbn; tile_map(tv, pbm, pbn);
        const int stage = ls & 1;
        const u32 bar = stage ? BAR1 : BAR0;
        const u32 dstA = TILES + stage * STAGEB;
        MBAR_EXPECT_TX(bar, 2 * TILE_BYTES);
        bulk_cp(dstA, XT + ((size_t)pbm * 64 + kt) * TILE_BYTES, TILE_BYTES, bar);
        bulk_cp(dstA + TILE_BYTES, WT + ((size_t)pbn * 64 + kt) * TILE_BYTES,
                TILE_BYTES, bar);
    };

    if (tid == 0) prefetch(0);

    int ls = 0;
    for (int w = 0; w < ntiles; w++) {
        int bm, bn; tile_map(bid + w * GRID, bm, bn);
        const int mBase = bm * BM, nBase = bn * BN;

        float acc[4][8][4];
        #pragma unroll
        for (int m = 0; m < 4; m++)
            #pragma unroll
            for (int n = 0; n < 8; n++)
                #pragma unroll
                for (int q = 0; q < 4; q++) acc[m][n][q] = 0.f;

        for (int kt = 0; kt < 64; kt++, ls++) {
            const int stage = ls & 1;
            MBAR_WAIT(stage ? BAR1 : BAR0, (ls >> 1) & 1);  // step ls data resident
            __syncthreads();   // all warps done with step ls-1 -> other stage free
            if (tid == 0 && ls + 1 < total) prefetch(ls + 1);

            const u32 Ab = TILES + stage * STAGEB;
            const u32 Bb = Ab + TILE_BYTES;
            #pragma unroll
            for (int kk = 0; kk < BK / 16; kk++) {
                u32 af[4][4];
                #pragma unroll
                for (int m = 0; m < 4; m++) {
                    int row = wm * 64 + m * 16 + (lane & 15);
                    u32 addr = Ab + sw128(row * 128 + (kk * 2 + (lane >> 4)) * 16);
                    asm volatile(
                        "ldmatrix.sync.aligned.m8n8.x4.shared.b16 {%0,%1,%2,%3}, [%4];\n"
                        : "=r"(af[m][0]), "=r"(af[m][1]), "=r"(af[m][2]), "=r"(af[m][3])
                        : "r"(addr));
                }
                u32 bf[8][2];
                #pragma unroll
                for (int np = 0; np < 4; np++) {
                    int grp = lane >> 3;
                    int row = wn * 64 + np * 16 + (grp >> 1) * 8 + (lane & 7);
                    u32 addr = Bb + sw128(row * 128 + (kk * 2 + (grp & 1)) * 16);
                    u32 q0, q1, q2, q3;
                    asm volatile(
                        "ldmatrix.sync.aligned.m8n8.x4.shared.b16 {%0,%1,%2,%3}, [%4];\n"
                        : "=r"(q0), "=r"(q1), "=r"(q2), "=r"(q3)
                        : "r"(addr));
                    bf[np * 2][0] = q0;     bf[np * 2][1] = q1;
                    bf[np * 2 + 1][0] = q2; bf[np * 2 + 1][1] = q3;
                }
                #pragma unroll
                for (int m = 0; m < 4; m++)
                    #pragma unroll
                    for (int n = 0; n < 8; n++)
                        asm volatile(
                            "mma.sync.aligned.m16n8k16.row.col.f32.f16.f16.f32 "
                            "{%0,%1,%2,%3}, {%4,%5,%6,%7}, {%8,%9}, {%0,%1,%2,%3};\n"
                            : "+f"(acc[m][n][0]), "+f"(acc[m][n][1]),
                              "+f"(acc[m][n][2]), "+f"(acc[m][n][3])
                            : "r"(af[m][0]), "r"(af[m][1]), "r"(af[m][2]), "r"(af[m][3]),
                              "r"(bf[n][0]), "r"(bf[n][1]));
            }
        }

        // epilogue (regs only; overlaps the already-issued next-tile bulk copy)
        #pragma unroll
        for (int n = 0; n < 8; n++) {
            int colBase = nBase + wn * 64 + n * 8 + 2 * (lane & 3);
            float b0 = __half2float(__float2half_rn(BIAS[colBase]));
            float b1 = __half2float(__float2half_rn(BIAS[colBase + 1]));
            #pragma unroll
            for (int m = 0; m < 4; m++) {
                int row0 = mBase + wm * 64 + m * 16 + (lane >> 2);
                float o00 = __half2float(__float2half_rn(
                              __half2float(__float2half_rn(acc[m][n][0])) + b0));
                float o01 = __half2float(__float2half_rn(
                              __half2float(__float2half_rn(acc[m][n][1])) + b1));
                float o10 = __half2float(__float2half_rn(
                              __half2float(__float2half_rn(acc[m][n][2])) + b0));
                float o11 = __half2float(__float2half_rn(
                              __half2float(__float2half_rn(acc[m][n][3])) + b1));
                *(float2*)(OUT + (size_t)row0 * NOUT + colBase) = make_float2(o00, o01);
                *(float2*)(OUT + (size_t)(row0 + 8) * NOUT + colBase) = make_float2(o10, o11);
            }
        }
    }
}

extern "C" void kernel_launch(void* const* d_in, const int* in_sizes, int n_in,
                              void* d_out, int out_size)
{
    const float* x    = nullptr;
    const int*   wp   = nullptr;
    const float* amax = nullptr;
    const float* bias = nullptr;
    for (int i = 0; i < n_in; i++) {
        switch (in_sizes[i]) {
            case 16777216: x    = (const float*)d_in[i]; break;
            case 22544384: wp   = (const int*)d_in[i];   break;
            case 704512:   amax = (const float*)d_in[i]; break;
            case 11008:    bias = (const float*)d_in[i]; break;
            default: break;
        }
    }
    float* out = (float*)d_out;

    convert_x_kernel<<<8192, 256>>>(x);
    dequant_w_kernel<<<22016, 256>>>(wp, amax);

    cudaFuncSetAttribute(nf4_mma_gemm,
                         cudaFuncAttributeMaxDynamicSharedMemorySize, SMEM_BYTES);
    nf4_mma_gemm<<<GRID, THREADS, SMEM_BYTES>>>(bias, out);
}

// round 15
// speedup vs baseline: 1.0405x; 1.0405x over previous
#include <cuda_runtime.h>
#include <cuda_fp16.h>
#include <cstdint>

// NF4 linear, 3-kernel plan (mma.sync path; tcgen05 unavailable on compute_103):
//   1) convert X fp32 -> fp16, TILE-MAJOR + PRE-SWIZZLED scratch
//   2) dequantize W -> fp16, TILE-MAJOR + PRE-SWIZZLED scratch
//   3) GEMM: out = fp16(XT @ WT^T) + fp16(bias), emitted fp32
// GEMM: BM=BN=128, BK=64, 4 warps @ 64x64, 2-stage bulk-copy pipeline, 3 CTAs/SM.
// R15: empty/full mbarrier protocol (no per-kt __syncthreads). R14's crash was a
// DOUBLE fill(1) (prologue + first loop iter) -> mbarrier over-arrival; fixed by
// filling only stage 0 in the prologue.

typedef unsigned int u32;

#define BM 128
#define BN 128
#define BK 64
#define THREADS 128
#define KDIM 4096
#define NOUT 11008
#define TILE_BYTES 16384                       // 128 rows x 128B (64 halfs)

// tile-major pre-swizzled scratch
__device__ __align__(1024) unsigned char XT[32u * 64u * 16384u];   // 32 MB
__device__ __align__(1024) unsigned char WT[86u * 64u * 16384u];   // 90 MB

__constant__ float c_nf4[16] = {
    -1.0f, -0.6961928009986877f, -0.5250730514526367f, -0.39491748809814453f,
    -0.28444138169288635f, -0.18477343022823334f, -0.09105003625154495f, 0.0f,
    0.07958029955625534f, 0.16093020141124725f, 0.24611230194568634f,
    0.33791524171829224f, 0.44070982933044434f, 0.5626170039176941f,
    0.8072066307067871f, 1.0f};

__device__ __forceinline__ u32 sw128(u32 off) { return off ^ ((off >> 3) & 0x70); }

#define MBAR_INIT(a, c) \
    asm volatile("mbarrier.init.shared.b64 [%0], %1;" :: "r"(a), "r"(c) : "memory")
#define MBAR_EXPECT_TX(a, tx) \
    asm volatile("mbarrier.arrive.expect_tx.shared.b64 _, [%0], %1;" \
                 :: "r"(a), "r"(tx) : "memory")
#define MBAR_ARRIVE(a) \
    asm volatile("mbarrier.arrive.shared.b64 _, [%0];" :: "r"(a) : "memory")
// relaxed wait (producer-side gating)
#define MBAR_WAIT(a, par) do {                                                       \
    u32 _mb = (a); u32 _p = (par); u32 _done;                                        \
    asm volatile("{ .reg .pred p; mbarrier.try_wait.parity.shared.b64 p, [%1], %2;"  \
                 " selp.b32 %0,1,0,p; }" : "=r"(_done) : "r"(_mb), "r"(_p) : "memory"); \
    while (!_done) {                                                                 \
        asm volatile("{ .reg .pred p; mbarrier.try_wait.parity.shared.b64 p, [%1], %2;" \
                     " selp.b32 %0,1,0,p; }" : "=r"(_done) : "r"(_mb), "r"(_p) : "memory"); \
    }                                                                                \
} while (0)
// acquire wait (consumer-side: orders subsequent smem reads after bulk writes)
#define MBAR_WAIT_ACQ(a, par) do {                                                   \
    u32 _mb = (a); u32 _p = (par); u32 _done;                                        \
    asm volatile("{ .reg .pred p; "                                                  \
                 "mbarrier.try_wait.parity.acquire.cta.shared::cta.b64 p, [%1], %2;" \
                 " selp.b32 %0,1,0,p; }" : "=r"(_done) : "r"(_mb), "r"(_p) : "memory"); \
    while (!_done) {                                                                 \
        asm volatile("{ .reg .pred p; "                                              \
                 "mbarrier.try_wait.parity.acquire.cta.shared::cta.b64 p, [%1], %2;" \
                 " selp.b32 %0,1,0,p; }" : "=r"(_done) : "r"(_mb), "r"(_p) : "memory"); \
    }                                                                                \
} while (0)

__device__ __forceinline__ void bulk_cp(u32 dst, const void* src, u32 bytes, u32 bar) {
    asm volatile(
        "cp.async.bulk.shared::cta.global.mbarrier::complete_tx::bytes "
        "[%0], [%1], %2, [%3];\n"
        :: "r"(dst), "l"(src), "r"(bytes), "r"(bar) : "memory");
}

// ---------------- prep kernels (tile-major, pre-swizzled output) ----------------
__global__ __launch_bounds__(256) void convert_x_kernel(const float* __restrict__ X) {
    int t = blockIdx.x * 256 + threadIdx.x;        // 2M chunks
    int tile = t >> 10, c = t & 1023;
    int bm = tile >> 6, kt = tile & 63;
    int r = c >> 3, j = c & 7;
    const float* xp = X + (size_t)(bm * 128 + r) * KDIM + kt * 64 + j * 8;
    float4 a = *(const float4*)xp, b = *(const float4*)(xp + 4);
    __half2 h0 = __floats2half2_rn(a.x, a.y), h1 = __floats2half2_rn(a.z, a.w);
    __half2 h2 = __floats2half2_rn(b.x, b.y), h3 = __floats2half2_rn(b.z, b.w);
    uint4 o;
    o.x = *(u32*)&h0; o.y = *(u32*)&h1; o.z = *(u32*)&h2; o.w = *(u32*)&h3;
    *(uint4*)(XT + (size_t)tile * TILE_BYTES + sw128(r * 128 + j * 16)) = o;
}

__global__ __launch_bounds__(256) void dequant_w_kernel(const int* __restrict__ WP,
                                                        const float* __restrict__ AM) {
    __shared__ float tab[16];
    if (threadIdx.x < 16) tab[threadIdx.x] = c_nf4[threadIdx.x];
    __syncthreads();
    int t = blockIdx.x * 256 + threadIdx.x;        // 5.63M chunks
    int tile = t >> 10, c = t & 1023;
    int bn = tile >> 6, kt = tile & 63;
    int r = c >> 3, j = c & 7;
    int n = bn * 128 + r;
    float s = AM[(size_t)n * 64 + kt];             // kt == absmax block index
    int4 v = *(const int4*)(WP + (size_t)n * 2048 + kt * 32 + j * 4);
    int vv[4] = {v.x, v.y, v.z, v.w};
    u32 o[4];
    #pragma unroll
    for (int q = 0; q < 4; q++) {                  // hi nibble = even elem
        __half2 h = __floats2half2_rn(tab[(vv[q] >> 4) & 15] * s,
                                      tab[vv[q] & 15] * s);
        o[q] = *(u32*)&h;
    }
    uint4 w; w.x = o[0]; w.y = o[1]; w.z = o[2]; w.w = o[3];
    *(uint4*)(WT + (size_t)tile * TILE_BYTES + sw128(r * 128 + j * 16)) = w;
}

// ---------------- GEMM ----------------
#define STAGEB (2 * TILE_BYTES)                    // A+B per stage = 32768
#define SMEM_BYTES (1024 + 2 * STAGEB)             // 66560

__global__ __launch_bounds__(THREADS, 3)
void nf4_mma_gemm(const float* __restrict__ BIAS, float* __restrict__ OUT)
{
    constexpr int STEPS = KDIM / BK;               // 64
    constexpr int NB = NOUT / BN;                  // 86
    constexpr int GRPM = 16;                       // m-tiles per swizzle group

    extern __shared__ unsigned char smem[];
    u32 sbase;
    asm("{ .reg .u64 t; cvta.to.shared.u64 t, %1; cvt.u32.u64 %0, t; }"
        : "=r"(sbase) : "l"(smem));
    const u32 FB0 = sbase, FB1 = sbase + 8;        // full barriers (tx, count 1)
    const u32 EB0 = sbase + 16, EB1 = sbase + 24;  // empty barriers (count 4)
    const u32 TILES = sbase + 1024;

    const int tid = threadIdx.x;
    const int lane = tid & 31;
    const int wid = tid >> 5;
    const int wm = wid >> 1;
    const int wn = wid & 1;

    const int bid = blockIdx.x;
    const int g = bid / (GRPM * NB), r = bid % (GRPM * NB);
    const int bm = g * GRPM + (r % GRPM), bn = r / GRPM;
    const int mBase = bm * BM, nBase = bn * BN;

    const unsigned char* xtile = XT + (size_t)bm * 64 * TILE_BYTES;
    const unsigned char* wtile = WT + (size_t)bn * 64 * TILE_BYTES;

    float acc[4][8][4];
    #pragma unroll
    for (int m = 0; m < 4; m++)
        #pragma unroll
        for (int n = 0; n < 8; n++)
            #pragma unroll
            for (int q = 0; q < 4; q++) acc[m][n][q] = 0.f;

    if (tid == 0) {
        MBAR_INIT(FB0, 1); MBAR_INIT(FB1, 1);
        MBAR_INIT(EB0, 4); MBAR_INIT(EB1, 4);      // one arrive per warp per use
    }
    __syncthreads();

    auto fill = [&](int j) {
        const int s = j & 1;
        const u32 bar = s ? FB1 : FB0;
        const u32 dstA = TILES + s * STAGEB;
        MBAR_EXPECT_TX(bar, 2 * TILE_BYTES);
        bulk_cp(dstA, xtile + (size_t)j * TILE_BYTES, TILE_BYTES, bar);
        bulk_cp(dstA + TILE_BYTES, wtile + (size_t)j * TILE_BYTES, TILE_BYTES, bar);
    };

    if (tid == 0) fill(0);                         // ONLY stage 0 (R14 bug fix)

    for (int kt = 0; kt < STEPS; kt++) {
        const int stage = kt & 1;

        // producer: issue fill kt+1 exactly once; stage reuse gated by the
        // empty barrier (arrivals from step kt-1), not a block barrier.
        if (tid == 0 && kt + 1 < STEPS) {
            const int j = kt + 1, s = j & 1;
            if (j >= 2) MBAR_WAIT(s ? EB1 : EB0, ((j >> 1) - 1) & 1);
            fill(j);
        }

        MBAR_WAIT_ACQ(stage ? FB1 : FB0, (kt >> 1) & 1);   // kt data resident

        const u32 Ab = TILES + stage * STAGEB;
        const u32 Bb = Ab + TILE_BYTES;
        #pragma unroll
        for (int kk = 0; kk < BK / 16; kk++) {
            u32 af[4][4];
            #pragma unroll
            for (int m = 0; m < 4; m++) {
                int row = wm * 64 + m * 16 + (lane & 15);
                u32 addr = Ab + sw128(row * 128 + (kk * 2 + (lane >> 4)) * 16);
                asm volatile(
                    "ldmatrix.sync.aligned.m8n8.x4.shared.b16 {%0,%1,%2,%3}, [%4];\n"
                    : "=r"(af[m][0]), "=r"(af[m][1]), "=r"(af[m][2]), "=r"(af[m][3])
                    : "r"(addr));
            }
            u32 bf[8][2];
            #pragma unroll
            for (int np = 0; np < 4; np++) {
                int grp = lane >> 3;
                int row = wn * 64 + np * 16 + (grp >> 1) * 8 + (lane & 7);
                u32 addr = Bb + sw128(row * 128 + (kk * 2 + (grp & 1)) * 16);
                u32 q0, q1, q2, q3;
                asm volatile(
                    "ldmatrix.sync.aligned.m8n8.x4.shared.b16 {%0,%1,%2,%3}, [%4];\n"
                    : "=r"(q0), "=r"(q1), "=r"(q2), "=r"(q3)
                    : "r"(addr));
                bf[np * 2][0] = q0;     bf[np * 2][1] = q1;
                bf[np * 2 + 1][0] = q2; bf[np * 2 + 1][1] = q3;
            }
            #pragma unroll
            for (int m = 0; m < 4; m++)
                #pragma unroll
                for (int n = 0; n < 8; n++)
                    asm volatile(
                        "mma.sync.aligned.m16n8k16.row.col.f32.f16.f16.f32 "
                        "{%0,%1,%2,%3}, {%4,%5,%6,%7}, {%8,%9}, {%0,%1,%2,%3};\n"
                        : "+f"(acc[m][n][0]), "+f"(acc[m][n][1]),
                          "+f"(acc[m][n][2]), "+f"(acc[m][n][3])
                        : "r"(af[m][0]), "r"(af[m][1]), "r"(af[m][2]), "r"(af[m][3]),
                          "r"(bf[n][0]), "r"(bf[n][1]));
        }

        // this warp is done reading 'stage' for step kt
        if (lane == 0) MBAR_ARRIVE(stage ? EB1 : EB0);
    }

    // epilogue: emulate fp16(dot)+fp16(bias) rounding, emit fp32
    #pragma unroll
    for (int n = 0; n < 8; n++) {
        int colBase = nBase + wn * 64 + n * 8 + 2 * (lane & 3);
        float b0 = __half2float(__float2half_rn(BIAS[colBase]));
        float b1 = __half2float(__float2half_rn(BIAS[colBase + 1]));
        #pragma unroll
        for (int m = 0; m < 4; m++) {
            int row0 = mBase + wm * 64 + m * 16 + (lane >> 2);
            float o00 = __half2float(__float2half_rn(
                          __half2float(__float2half_rn(acc[m][n][0])) + b0));
            float o01 = __half2float(__float2half_rn(
                          __half2float(__float2half_rn(acc[m][n][1])) + b1));
            float o10 = __half2float(__float2half_rn(
                          __half2float(__float2half_rn(acc[m][n][2])) + b0));
            float o11 = __half2float(__float2half_rn(
                          __half2float(__float2half_rn(acc[m][n][3])) + b1));
            *(float2*)(OUT + (size_t)row0 * NOUT + colBase) = make_float2(o00, o01);
            *(float2*)(OUT + (size_t)(row0 + 8) * NOUT + colBase) = make_float2(o10, o11);
        }
    }
}

extern "C" void kernel_launch(void* const* d_in, const int* in_sizes, int n_in,
                              void* d_out, int out_size)
{
    const float* x    = nullptr;
    const int*   wp   = nullptr;
    const float* amax = nullptr;
    const float* bias = nullptr;
    for (int i = 0; i < n_in; i++) {
        switch (in_sizes[i]) {
            case 16777216: x    = (const float*)d_in[i]; break;
            case 22544384: wp   = (const int*)d_in[i];   break;
            case 704512:   amax = (const float*)d_in[i]; break;
            case 11008:    bias = (const float*)d_in[i]; break;
            default: break;
        }
    }
    float* out = (float*)d_out;

    convert_x_kernel<<<8192, 256>>>(x);
    dequant_w_kernel<<<22016, 256>>>(wp, amax);

    cudaFuncSetAttribute(nf4_mma_gemm,
                         cudaFuncAttributeMaxDynamicSharedMemorySize, SMEM_BYTES);
    nf4_mma_gemm<<<(4096 / BM) * (11008 / BN), THREADS, SMEM_BYTES>>>(bias, out);
}

// round 17
// speedup vs baseline: 1.0892x; 1.0468x over previous
#include <cuda_runtime.h>
#include <cuda_fp16.h>
#include <cstdint>

// NF4 linear (mma.sync path; tcgen05 unavailable on compute_103):
//   1) ONE merged prep kernel: X fp32->fp16 and W dequant, both written
//      TILE-MAJOR + PRE-SWIZZLED.
//   2) GEMM (exact R11 structure): BM=BN=128, BK=64, 4 warps @ 64x64,
//      2-stage bulk-copy pipeline, one __syncthreads/kt, 3 CTAs/SM.
// Tile map: bm = bid%32, bn = bid/32 -> whole 32MB XT slab L2-resident,
// W makes a single DRAM pass.
// (Resubmission of R16 — round died to a broker/container failure before the
//  kernel ever ran; source audited hang-free: uniform barriers per block,
//  proven mbarrier accounting, exact R11 GEMM loop.)

typedef unsigned int u32;

#define BM 128
#define BN 128
#define BK 64
#define THREADS 128
#define KDIM 4096
#define NOUT 11008
#define TILE_BYTES 16384                       // 128 rows x 128B (64 halfs)

// tile-major pre-swizzled scratch
__device__ __align__(1024) unsigned char XT[32u * 64u * 16384u];   // 32 MB
__device__ __align__(1024) unsigned char WT[86u * 64u * 16384u];   // 90 MB

__constant__ float c_nf4[16] = {
    -1.0f, -0.6961928009986877f, -0.5250730514526367f, -0.39491748809814453f,
    -0.28444138169288635f, -0.18477343022823334f, -0.09105003625154495f, 0.0f,
    0.07958029955625534f, 0.16093020141124725f, 0.24611230194568634f,
    0.33791524171829224f, 0.44070982933044434f, 0.5626170039176941f,
    0.8072066307067871f, 1.0f};

__device__ __forceinline__ u32 sw128(u32 off) { return off ^ ((off >> 3) & 0x70); }

#define MBAR_INIT(a, c) \
    asm volatile("mbarrier.init.shared.b64 [%0], %1;" :: "r"(a), "r"(c) : "memory")
#define MBAR_EXPECT_TX(a, tx) \
    asm volatile("mbarrier.arrive.expect_tx.shared.b64 _, [%0], %1;" \
                 :: "r"(a), "r"(tx) : "memory")
#define MBAR_WAIT(a, par) do {                                                       \
    u32 _mb = (a); u32 _p = (par); u32 _done;                                        \
    asm volatile("{ .reg .pred p; mbarrier.try_wait.parity.shared.b64 p, [%1], %2;"  \
                 " selp.b32 %0,1,0,p; }" : "=r"(_done) : "r"(_mb), "r"(_p) : "memory"); \
    while (!_done) {                                                                 \
        asm volatile("{ .reg .pred p; mbarrier.try_wait.parity.shared.b64 p, [%1], %2;" \
                     " selp.b32 %0,1,0,p; }" : "=r"(_done) : "r"(_mb), "r"(_p) : "memory"); \
    }                                                                                \
} while (0)

__device__ __forceinline__ void bulk_cp(u32 dst, const void* src, u32 bytes, u32 bar) {
    asm volatile(
        "cp.async.bulk.shared::cta.global.mbarrier::complete_tx::bytes "
        "[%0], [%1], %2, [%3];\n"
        :: "r"(dst), "l"(src), "r"(bytes), "r"(bar) : "memory");
}

// ---------------- merged prep kernel ----------------
// blocks [0, 8192):   X convert   (2M chunks)
// blocks [8192, 30208): W dequant (5.63M chunks)
#define XBLOCKS 8192
__global__ __launch_bounds__(256) void prep_kernel(const float* __restrict__ X,
                                                   const int*   __restrict__ WP,
                                                   const float* __restrict__ AM) {
    if (blockIdx.x < XBLOCKS) {
        int t = blockIdx.x * 256 + threadIdx.x;
        int tile = t >> 10, c = t & 1023;
        int bm = tile >> 6, kt = tile & 63;
        int r = c >> 3, j = c & 7;
        const float* xp = X + (size_t)(bm * 128 + r) * KDIM + kt * 64 + j * 8;
        float4 a = *(const float4*)xp, b = *(const float4*)(xp + 4);
        __half2 h0 = __floats2half2_rn(a.x, a.y), h1 = __floats2half2_rn(a.z, a.w);
        __half2 h2 = __floats2half2_rn(b.x, b.y), h3 = __floats2half2_rn(b.z, b.w);
        uint4 o;
        o.x = *(u32*)&h0; o.y = *(u32*)&h1; o.z = *(u32*)&h2; o.w = *(u32*)&h3;
        *(uint4*)(XT + (size_t)tile * TILE_BYTES + sw128(r * 128 + j * 16)) = o;
    } else {
        __shared__ float tab[16];
        if (threadIdx.x < 16) tab[threadIdx.x] = c_nf4[threadIdx.x];
        __syncthreads();
        int t = (blockIdx.x - XBLOCKS) * 256 + threadIdx.x;
        int tile = t >> 10, c = t & 1023;
        int bn = tile >> 6, kt = tile & 63;
        int r = c >> 3, j = c & 7;
        int n = bn * 128 + r;
        float s = AM[(size_t)n * 64 + kt];         // kt == absmax block index
        int4 v = *(const int4*)(WP + (size_t)n * 2048 + kt * 32 + j * 4);
        int vv[4] = {v.x, v.y, v.z, v.w};
        u32 o[4];
        #pragma unroll
        for (int q = 0; q < 4; q++) {              // hi nibble = even elem
            __half2 h = __floats2half2_rn(tab[(vv[q] >> 4) & 15] * s,
                                          tab[vv[q] & 15] * s);
            o[q] = *(u32*)&h;
        }
        uint4 w; w.x = o[0]; w.y = o[1]; w.z = o[2]; w.w = o[3];
        *(uint4*)(WT + (size_t)tile * TILE_BYTES + sw128(r * 128 + j * 16)) = w;
    }
}

// ---------------- GEMM (exact R11 loop) ----------------
#define STAGEB (2 * TILE_BYTES)                    // A+B per stage = 32768
#define SMEM_BYTES (1024 + 2 * STAGEB)             // 66560

__global__ __launch_bounds__(THREADS, 3)
void nf4_mma_gemm(const float* __restrict__ BIAS, float* __restrict__ OUT)
{
    constexpr int STEPS = KDIM / BK;               // 64

    extern __shared__ unsigned char smem[];
    u32 sbase;
    asm("{ .reg .u64 t; cvta.to.shared.u64 t, %1; cvt.u32.u64 %0, t; }"
        : "=r"(sbase) : "l"(smem));
    const u32 BAR0 = sbase, BAR1 = sbase + 8;
    const u32 TILES = sbase + 1024;

    const int tid = threadIdx.x;
    const int lane = tid & 31;
    const int wid = tid >> 5;
    const int wm = wid >> 1;
    const int wn = wid & 1;

    // GRPM=32 tile map: all 32 m-tiles in flight; XT slab L2-resident;
    // W streamed exactly once from DRAM.
    const int bid = blockIdx.x;
    const int bm = bid & 31, bn = bid >> 5;
    const int mBase = bm * BM, nBase = bn * BN;

    const unsigned char* xtile = XT + (size_t)bm * 64 * TILE_BYTES;
    const unsigned char* wtile = WT + (size_t)bn * 64 * TILE_BYTES;

    float acc[4][8][4];
    #pragma unroll
    for (int m = 0; m < 4; m++)
        #pragma unroll
        for (int n = 0; n < 8; n++)
            #pragma unroll
            for (int q = 0; q < 4; q++) acc[m][n][q] = 0.f;

    if (tid == 0) { MBAR_INIT(BAR0, 1); MBAR_INIT(BAR1, 1); }
    __syncthreads();

    auto prefetch = [&](int kt) {
        if (tid == 0) {
            const int stage = kt & 1;
            const u32 bar = stage ? BAR1 : BAR0;
            const u32 dstA = TILES + stage * STAGEB;
            MBAR_EXPECT_TX(bar, 2 * TILE_BYTES);
            bulk_cp(dstA, xtile + (size_t)kt * TILE_BYTES, TILE_BYTES, bar);
            bulk_cp(dstA + TILE_BYTES, wtile + (size_t)kt * TILE_BYTES,
                    TILE_BYTES, bar);
        }
    };

    prefetch(0);

    for (int kt = 0; kt < STEPS; kt++) {
        const int stage = kt & 1;
        MBAR_WAIT(stage ? BAR1 : BAR0, (kt >> 1) & 1);   // data for kt resident
        __syncthreads();    // all warps done computing kt-1 (other stage reusable)
        if (kt + 1 < STEPS) prefetch(kt + 1);            // overlaps compute of kt

        const u32 Ab = TILES + stage * STAGEB;
        const u32 Bb = Ab + TILE_BYTES;
        #pragma unroll
        for (int kk = 0; kk < BK / 16; kk++) {
            u32 af[4][4];
            #pragma unroll
            for (int m = 0; m < 4; m++) {
                int row = wm * 64 + m * 16 + (lane & 15);
                u32 addr = Ab + sw128(row * 128 + (kk * 2 + (lane >> 4)) * 16);
                asm volatile(
                    "ldmatrix.sync.aligned.m8n8.x4.shared.b16 {%0,%1,%2,%3}, [%4];\n"
                    : "=r"(af[m][0]), "=r"(af[m][1]), "=r"(af[m][2]), "=r"(af[m][3])
                    : "r"(addr));
            }
            u32 bf[8][2];
            #pragma unroll
            for (int np = 0; np < 4; np++) {
                int grp = lane >> 3;
                int row = wn * 64 + np * 16 + (grp >> 1) * 8 + (lane & 7);
                u32 addr = Bb + sw128(row * 128 + (kk * 2 + (grp & 1)) * 16);
                u32 q0, q1, q2, q3;
                asm volatile(
                    "ldmatrix.sync.aligned.m8n8.x4.shared.b16 {%0,%1,%2,%3}, [%4];\n"
                    : "=r"(q0), "=r"(q1), "=r"(q2), "=r"(q3)
                    : "r"(addr));
                bf[np * 2][0] = q0;     bf[np * 2][1] = q1;
                bf[np * 2 + 1][0] = q2; bf[np * 2 + 1][1] = q3;
            }
            #pragma unroll
            for (int m = 0; m < 4; m++)
                #pragma unroll
                for (int n = 0; n < 8; n++)
                    asm volatile(
                        "mma.sync.aligned.m16n8k16.row.col.f32.f16.f16.f32 "
                        "{%0,%1,%2,%3}, {%4,%5,%6,%7}, {%8,%9}, {%0,%1,%2,%3};\n"
                        : "+f"(acc[m][n][0]), "+f"(acc[m][n][1]),
                          "+f"(acc[m][n][2]), "+f"(acc[m][n][3])
                        : "r"(af[m][0]), "r"(af[m][1]), "r"(af[m][2]), "r"(af[m][3]),
                          "r"(bf[n][0]), "r"(bf[n][1]));
        }
    }

    // epilogue: emulate fp16(dot)+fp16(bias) rounding, emit fp32
    #pragma unroll
    for (int n = 0; n < 8; n++) {
        int colBase = nBase + wn * 64 + n * 8 + 2 * (lane & 3);
        float b0 = __half2float(__float2half_rn(BIAS[colBase]));
        float b1 = __half2float(__float2half_rn(BIAS[colBase + 1]));
        #pragma unroll
        for (int m = 0; m < 4; m++) {
            int row0 = mBase + wm * 64 + m * 16 + (lane >> 2);
            float o00 = __half2float(__float2half_rn(
                          __half2float(__float2half_rn(acc[m][n][0])) + b0));
            float o01 = __half2float(__float2half_rn(
                          __half2float(__float2half_rn(acc[m][n][1])) + b1));
            float o10 = __half2float(__float2half_rn(
                          __half2float(__float2half_rn(acc[m][n][2])) + b0));
            float o11 = __half2float(__float2half_rn(
                          __half2float(__float2half_rn(acc[m][n][3])) + b1));
            *(float2*)(OUT + (size_t)row0 * NOUT + colBase) = make_float2(o00, o01);
            *(float2*)(OUT + (size_t)(row0 + 8) * NOUT + colBase) = make_float2(o10, o11);
        }
    }
}

extern "C" void kernel_launch(void* const* d_in, const int* in_sizes, int n_in,
                              void* d_out, int out_size)
{
    const float* x    = nullptr;
    const int*   wp   = nullptr;
    const float* amax = nullptr;
    const float* bias = nullptr;
    for (int i = 0; i < n_in; i++) {
        switch (in_sizes[i]) {
            case 16777216: x    = (const float*)d_in[i]; break;
            case 22544384: wp   = (const int*)d_in[i];   break;
            case 704512:   amax = (const float*)d_in[i]; break;
            case 11008:    bias = (const float*)d_in[i]; break;
            default: break;
        }
    }
    float* out = (float*)d_out;

    prep_kernel<<<30208, 256>>>(x, wp, amax);     // 8192 X-blocks + 22016 W-blocks

    cudaFuncSetAttribute(nf4_mma_gemm,
                         cudaFuncAttributeMaxDynamicSharedMemorySize, SMEM_BYTES);
    nf4_mma_gemm<<<(4096 / BM) * (11008 / BN), THREADS, SMEM_BYTES>>>(bias, out);
}